// round 14
// baseline (speedup 1.0000x reference)
#include <cuda_runtime.h>
#include <cstdint>

// CRF loss, bidirectional scaled forward algorithm, TWO BATCH ROWS PER CTA.
// CTA = 128 threads handles rows (b0, b1):
//   warps 0-1 (group F, named bar 1): alpha forward of BOTH rows
//   warps 2-3 (group B, named bar 2): beta backward of BOTH rows
// A thread's packed-E registers depend only on (direction, column), so the
// two rows share them. Each period advances both rows one step -> barrier,
// loop overhead, and chain exposure amortized 2x. fma.rn.f32x2 inner loops,
// exact pow-2 rescaling per row per step. Z_r = sum_i alpha_m[i]*beta_m[i].

constexpr int TT = 50;
constexpr int LL = 256;
constexpr int NTH = 128;
constexpr int STARTT = TT - 2;
constexpr int STOPT  = TT - 1;

#define LOG2E 1.4426950408889634f
#define LN2F  0.6931471805599453f

__device__ float    g_partial[1024];
__device__ unsigned g_done = 0;

__device__ __forceinline__ float ex2(float x) {
    float r;
    asm("ex2.approx.ftz.f32 %0, %1;" : "=f"(r) : "f"(x));
    return r;
}

#define PACK2(d, lo, hi) \
    asm("mov.b64 %0, {%1, %2};" : "=l"(d) : "f"(lo), "f"(hi))
#define UNPACK2(lo, hi, s) \
    asm("mov.b64 {%0, %1}, %2;" : "=f"(lo), "=f"(hi) : "l"(s))
#define FFMA2(d, a, b, c) \
    asm("fma.rn.f32x2 %0, %1, %2, %3;" : "=l"(d) : "l"(a), "l"(b), "l"(c))
#define FMUL2(d, a, b) \
    asm("mul.rn.f32x2 %0, %1, %2;" : "=l"(d) : "l"(a), "l"(b))
#define FADD2(d, a, b) \
    asm("add.rn.f32x2 %0, %1, %2;" : "=l"(d) : "l"(a), "l"(b))
#define LDS_V2U64(q0, q1, addr) \
    asm volatile("ld.shared.v2.u64 {%0, %1}, [%2];" \
                 : "=l"(q0), "=l"(q1) : "r"(addr))

__device__ __forceinline__ void barg(int id) {    // group barrier, 64 threads
    asm volatile("bar.sync %0, 64;" :: "r"(id));
}

// 64-thread group sum; slot = 2 dedicated floats per call site
__device__ __forceinline__ float groupSum(float v, volatile float* slot, int id) {
#pragma unroll
    for (int o = 16; o; o >>= 1) v += __shfl_xor_sync(0xffffffffu, v, o);
    if ((threadIdx.x & 31) == 0) slot[(threadIdx.x >> 5) & 1] = v;
    barg(id);
    return slot[0] + slot[1];
}

// fused 2-row dot: both rows vs the SAME packed E; exact pow2 rescale each
#define DOT2(PC0, PC1, EF0, EF1, R0V, R1V, K0V, K1V)                        \
    {                                                                       \
        unsigned sa0_ = (unsigned)__cvta_generic_to_shared(PC0);            \
        unsigned sa1_ = (unsigned)__cvta_generic_to_shared(PC1);            \
        uint64_t qa0, qa1, qb0, qb1;                                        \
        LDS_V2U64(qa0, qa1, sa0_);                                          \
        LDS_V2U64(qb0, qb1, sa1_);                                          \
        float x0_, x1_, x2_, x3_;                                           \
        UNPACK2(x0_, x1_, qa0); UNPACK2(x2_, x3_, qa1);                     \
        float m0_ = fmaxf(fmaxf(x1_, x2_), x3_);                            \
        UNPACK2(x0_, x1_, qb0); UNPACK2(x2_, x3_, qb1);                     \
        float m1_ = fmaxf(fmaxf(x1_, x2_), x3_);                            \
        K0V = (__float_as_int(m0_) >> 23) - 127;                            \
        K1V = (__float_as_int(m1_) >> 23) - 127;                            \
        float sf0_ = __int_as_float((127 - K0V) << 23) * (EF0);             \
        float sf1_ = __int_as_float((127 - K1V) << 23) * (EF1);             \
        uint64_t A0_, A1_, A2_, A3_, C0_, C1_, C2_, C3_;                    \
        FMUL2(A0_, qa0, E[0]); FMUL2(A1_, qa1, E[1]);                       \
        FMUL2(C0_, qb0, E[0]); FMUL2(C1_, qb1, E[1]);                       \
        LDS_V2U64(qa0, qa1, sa0_ + 16);                                     \
        LDS_V2U64(qb0, qb1, sa1_ + 16);                                     \
        FMUL2(A2_, qa0, E[2]); FMUL2(A3_, qa1, E[3]);                       \
        FMUL2(C2_, qb0, E[2]); FMUL2(C3_, qb1, E[3]);                       \
        _Pragma("unroll")                                                   \
        for (int q = 2; q < 13; q++) {                                      \
            LDS_V2U64(qa0, qa1, sa0_ + q * 16);                             \
            LDS_V2U64(qb0, qb1, sa1_ + q * 16);                             \
            FFMA2(A0_, qa0, E[2 * q], A0_);                                 \
            FFMA2(A1_, qa1, E[2 * q + 1], A1_);                             \
            FFMA2(C0_, qb0, E[2 * q], C0_);                                 \
            FFMA2(C1_, qb1, E[2 * q + 1], C1_);                             \
            uint64_t t_;                                                    \
            t_ = A0_; A0_ = A2_; A2_ = t_;                                  \
            t_ = A1_; A1_ = A3_; A3_ = t_;                                  \
            t_ = C0_; C0_ = C2_; C2_ = t_;                                  \
            t_ = C1_; C1_ = C3_; C3_ = t_;                                  \
        }                                                                   \
        FADD2(A0_, A0_, A2_); FADD2(A1_, A1_, A3_); FADD2(A0_, A0_, A1_);   \
        FADD2(C0_, C0_, C2_); FADD2(C1_, C1_, C3_); FADD2(C0_, C0_, C1_);   \
        float l0_, h0_, l1_, h1_;                                           \
        UNPACK2(l0_, h0_, A0_); UNPACK2(l1_, h1_, C0_);                     \
        R0V = (l0_ + h0_) * sf0_;                                           \
        R1V = (l1_ + h1_) * sf1_;                                           \
    }

__global__ void __launch_bounds__(NTH, 1)
crf_kernel(const float* __restrict__ feats, const float* __restrict__ trans,
           const int* __restrict__ tags, const int* __restrict__ mask,
           float* __restrict__ out, int Btot) {
    __shared__ __align__(16) float Ab0[2][64], Ab1[2][64];  // alpha rows 0,1
    __shared__ __align__(16) float Bb0[2][64], Bb1[2][64];  // beta  rows 0,1
    __shared__ float redF[8];
    __shared__ int s_len[2];
    __shared__ int s_kb0, s_kb1, s_cb0, s_cb1;
    __shared__ unsigned s_rank;

    const int b0   = blockIdx.x * 2;
    const bool has1 = (b0 + 1 < Btot);
    const int b1   = has1 ? (b0 + 1) : b0;
    const int tid  = threadIdx.x;
    const bool isF = (tid < 64);
    const int g    = tid & 63;
    const bool gv  = (g < TT);
    const int gc   = gv ? g : (TT - 1);
    const int bid  = isF ? 1 : 2;

    if (tid == 0) { s_len[0] = 0; s_len[1] = 0; }
    __syncthreads();

    // ---- lengths: F counts row0, B counts row1 (mask is a 0/1 prefix) ----
    {
        const int4* m4 = (const int4*)(mask + (size_t)(isF ? b0 : b1) * LL);
        int4 v = m4[g];
        int c = (v.x != 0) + (v.y != 0) + (v.z != 0) + (v.w != 0);
#pragma unroll
        for (int o = 16; o; o >>= 1) c += __shfl_xor_sync(0xffffffffu, c, o);
        if ((g & 31) == 0) atomicAdd(&s_len[isF ? 0 : 1], c);
    }

    // ---- packed E (direction+column only -> shared by both rows) ----
    uint64_t E[26];
    {
        const float* tb = isF ? (trans + gc) : (trans + gc * TT);
        const int    ts = isF ? TT : 1;
#pragma unroll
        for (int x = 0; x < 26; x++) {
            int i0 = 2 * x, i1 = 2 * x + 1;
            float e0 = (gv && i0 < TT) ? ex2(tb[i0 * ts] * LOG2E) : 0.f;
            float e1 = (gv && i1 < TT) ? ex2(tb[i1 * ts] * LOG2E) : 0.f;
            PACK2(E[x], e0, e1);
        }
    }

    const float* fb0 = feats + (size_t)b0 * LL * TT;
    const float* fb1 = feats + (size_t)b1 * LL * TT;
    const float s0   = trans[STARTT * TT + 1];
    const float tref = trans[1 * TT + STOPT];
    const float C2f  = s0 * LOG2E;

    __syncthreads();
    const int len0 = s_len[0], len1 = s_len[1];
    const int nf0 = (len0 - 1) >> 1, nb0 = (len0 - 1) - nf0;
    const int nf1 = (len1 - 1) >> 1, nb1 = (len1 - 1) - nf1;

    // ---- inits ----
    if (isF) {
        Ab0[0][g] = gv ? ex2((fb0[gc] + trans[STARTT * TT + gc] - s0) * LOG2E) : 0.f;
        Ab1[0][g] = gv ? ex2((fb1[gc] + trans[STARTT * TT + gc] - s0) * LOG2E) : 0.f;
    } else {
        float w = gv ? ex2((trans[gc * TT + STOPT] - tref) * LOG2E) : 0.f;
        float f0 = (nb0 > 0) ? ex2(fb0[(len0 - 1) * TT + gc] * LOG2E) : 1.f;
        float f1 = (nb1 > 0) ? ex2(fb1[(len1 - 1) * TT + gc] * LOG2E) : 1.f;
        Bb0[0][g] = gv ? w * f0 : 0.f;
        Bb1[0][g] = gv ? w * f1 : 0.f;
    }
    int k0 = 0, k1 = 0, cur0 = 0, cur1 = 0;
    float gsum0 = 0.f, gsum1 = 0.f;
    barg(bid);       // group-local: each group reads only its own buffers

    if (isF) {
        // ---- forward both rows ----
        float fc0 = fb0[min(1, len0 - 1) * TT + gc];
        float fn0 = fb0[min(2, len0 - 1) * TT + gc];
        float fc1 = fb1[min(1, len1 - 1) * TT + gc];
        float fn1 = fb1[min(2, len1 - 1) * TT + gc];
        const int nmax = max(nf0, nf1);
        for (int s = 1; s <= nmax; ++s) {
            float ef0 = ex2(fc0 * LOG2E), ef1 = ex2(fc1 * LOG2E);
            fc0 = fn0; fn0 = fb0[min(s + 2, len0 - 1) * TT + gc];
            fc1 = fn1; fn1 = fb1[min(s + 2, len1 - 1) * TT + gc];
            float r0v, r1v; int kk0, kk1;
            DOT2(Ab0[cur0], Ab1[cur1], ef0, ef1, r0v, r1v, kk0, kk1);
            if (s <= nf0) { Ab0[cur0 ^ 1][g] = r0v; k0 += kk0; cur0 ^= 1; }
            if (s <= nf1) { Ab1[cur1 ^ 1][g] = r1v; k1 += kk1; cur1 ^= 1; }
            barg(1);
        }
        // ---- gold scores (while B finishes its longer loop) ----
        float gl0 = 0.f, gl1 = 0.f;
        const int* tg0 = tags + (size_t)b0 * LL;
        const int* tg1 = tags + (size_t)b1 * LL;
        for (int t = g; t < len0; t += 64) {
            int tg = tg0[t];
            int pv = (t == 0) ? STARTT : tg0[t - 1];
            gl0 += fb0[t * TT + tg] + trans[pv * TT + tg];
        }
        for (int t = g; t < len1; t += 64) {
            int tg = tg1[t];
            int pv = (t == 0) ? STARTT : tg1[t - 1];
            gl1 += fb1[t * TT + tg] + trans[pv * TT + tg];
        }
        gsum0 = groupSum(gl0, redF + 0, 1);
        gsum1 = groupSum(gl1, redF + 2, 1);
    } else {
        // ---- backward both rows (final step per row excludes ef_m) ----
        float fc0 = fb0[max(len0 - 2, 0) * TT + gc];
        float fn0 = fb0[max(len0 - 3, 0) * TT + gc];
        float fc1 = fb1[max(len1 - 2, 0) * TT + gc];
        float fn1 = fb1[max(len1 - 3, 0) * TT + gc];
        const int nmax = max(nb0, nb1);
        for (int s = 1; s <= nmax; ++s) {
            float ef0 = (s == nb0) ? 1.0f : ex2(fc0 * LOG2E);
            float ef1 = (s == nb1) ? 1.0f : ex2(fc1 * LOG2E);
            fc0 = fn0; fn0 = fb0[max(len0 - 3 - s, 0) * TT + gc];
            fc1 = fn1; fn1 = fb1[max(len1 - 3 - s, 0) * TT + gc];
            float r0v, r1v; int kk0, kk1;
            DOT2(Bb0[cur0], Bb1[cur1], ef0, ef1, r0v, r1v, kk0, kk1);
            if (s <= nb0) { Bb0[cur0 ^ 1][g] = r0v; k0 += kk0; cur0 ^= 1; }
            if (s <= nb1) { Bb1[cur1 ^ 1][g] = r1v; k1 += kk1; cur1 ^= 1; }
            barg(2);
        }
        if (tid == 64) { s_kb0 = k0; s_kb1 = k1; s_cb0 = cur0; s_cb1 = cur1; }
    }
    __syncthreads();   // cross-group: beta buffers + kb/cb now visible

    if (isF) {
        // ---- midpoint combine, both rows ----
        float z0 = Ab0[cur0][g] * Bb0[s_cb0][g];
        float z1 = Ab1[cur1][g] * Bb1[s_cb1][g];
        float zs0 = groupSum(z0, redF + 4, 1);
        float zs1 = groupSum(z1, redF + 6, 1);
        if (tid == 0) {
            const int* tg0 = tags + (size_t)b0 * LL;
            const int* tg1 = tags + (size_t)b1 * LL;
            float fwd0 = (log2f(zs0) + C2f + (float)(k0 + s_kb0)) * LN2F + tref;
            float fwd1 = (log2f(zs1) + C2f + (float)(k1 + s_kb1)) * LN2F + tref;
            float gold0 = gsum0 + trans[tg0[len0 - 1] * TT + STOPT];
            float gold1 = gsum1 + trans[tg1[len1 - 1] * TT + STOPT];
            g_partial[b0] = fwd0 - gold0;
            if (has1) g_partial[b0 + 1] = fwd1 - gold1;
        }
    }

    // ---- fused finalize: last CTA sums all partials (fixed order) ----
    __threadfence();
    if (tid == 0) s_rank = atomicAdd(&g_done, 1u);
    __syncthreads();
    if (s_rank == gridDim.x - 1) {
        if (tid < 32) {
            float acc = 0.f;
            for (int i = tid; i < Btot; i += 32) {
                float v;
                asm volatile("ld.global.cg.f32 %0, [%1];" : "=f"(v)
                             : "l"(&g_partial[i]));
                acc += v;
            }
#pragma unroll
            for (int o = 16; o; o >>= 1)
                acc += __shfl_xor_sync(0xffffffffu, acc, o);
            if (tid == 0) {
                *out = acc;
                g_done = 0;   // reset for next graph replay
            }
        }
    }
}

extern "C" void kernel_launch(void* const* d_in, const int* in_sizes, int n_in,
                              void* d_out, int out_size) {
    const float* feats = (const float*)d_in[0];
    const float* trans = (const float*)d_in[1];
    const int*   tags  = (const int*)d_in[2];
    const int*   mask  = (const int*)d_in[3];
    int B = in_sizes[0] / (LL * TT);
    int grid = (B + 1) / 2;

    crf_kernel<<<grid, NTH>>>(feats, trans, tags, mask, (float*)d_out, B);
}

// round 15
// speedup vs baseline: 1.3162x; 1.3162x over previous
#include <cuda_runtime.h>
#include <cstdint>

// CRF loss via bidirectional scaled forward algorithm, f32x2-packed inner loop.
// One 128-thread CTA per batch row: warps 0-1 alpha forward (t=0..m), warps
// 2-3 beta backward (t=len-1..m); Z = sum_i alpha_m[i]*beta_m[i]. Each group
// has its own named barrier and tight loop. 50-term dot product per thread =
// 26 fma.rn.f32x2 vs pre-packed E. Exact pow-2 rescaling every SECOND step
// (pivot = max P[1..3]); two unscaled steps bounded by ~2^39 — safe in fp32.

constexpr int TT = 50;
constexpr int LL = 256;
constexpr int NTH = 128;
constexpr int STARTT = TT - 2;
constexpr int STOPT  = TT - 1;

#define LOG2E 1.4426950408889634f
#define LN2F  0.6931471805599453f

__device__ float    g_partial[1024];
__device__ unsigned g_done = 0;

__device__ __forceinline__ float ex2(float x) {
    float r;
    asm("ex2.approx.ftz.f32 %0, %1;" : "=f"(r) : "f"(x));
    return r;
}

__device__ __forceinline__ void barg(int id) {    // group barrier, 64 threads
    asm volatile("bar.sync %0, 64;" :: "r"(id));
}

#define PACK2(d, lo, hi) \
    asm("mov.b64 %0, {%1, %2};" : "=l"(d) : "f"(lo), "f"(hi))
#define UNPACK2(lo, hi, s) \
    asm("mov.b64 {%0, %1}, %2;" : "=f"(lo), "=f"(hi) : "l"(s))
#define FFMA2(d, a, b, c) \
    asm("fma.rn.f32x2 %0, %1, %2, %3;" : "=l"(d) : "l"(a), "l"(b), "l"(c))
#define FMUL2(d, a, b) \
    asm("mul.rn.f32x2 %0, %1, %2;" : "=l"(d) : "l"(a), "l"(b))
#define FADD2(d, a, b) \
    asm("add.rn.f32x2 %0, %1, %2;" : "=l"(d) : "l"(a), "l"(b))
#define LDS_V2U64(q0, q1, addr) \
    asm volatile("ld.shared.v2.u64 {%0, %1}, [%2];" \
                 : "=l"(q0), "=l"(q1) : "r"(addr))

__device__ __forceinline__ float blockSum(float v, volatile float* red) {
#pragma unroll
    for (int o = 16; o; o >>= 1) v += __shfl_xor_sync(0xffffffffu, v, o);
    if ((threadIdx.x & 31) == 0) red[threadIdx.x >> 5] = v;
    __syncthreads();
    v = (red[0] + red[1]) + (red[2] + red[3]);
    __syncthreads();
    return v;
}

__global__ void __launch_bounds__(NTH, 1)
crf_kernel(const float* __restrict__ feats, const float* __restrict__ trans,
           const int* __restrict__ tags, const int* __restrict__ mask,
           float* __restrict__ out) {
    __shared__ __align__(16) float Ab[2][64];   // alpha ping-pong
    __shared__ __align__(16) float Bb[2][64];   // beta  ping-pong
    __shared__ float red[4];
    __shared__ int s_len, s_kf, s_kb;
    __shared__ unsigned s_rank;

    const int b    = blockIdx.x;
    const int tid  = threadIdx.x;
    const bool isF = (tid < 64);       // forward group = warps 0-1
    const int g    = tid & 63;         // state index within group
    const bool gv  = (g < TT);
    const int gc   = gv ? g : (TT - 1);
    const int bid  = isF ? 1 : 2;

    if (tid == 0) s_len = 0;
    __syncthreads();

    // ---- sequence length (mask is a 0/1 prefix) ----
    {
        const int2* m2 = (const int2*)(mask + (size_t)b * LL);
        int2 v = m2[tid];
        int c = (v.x != 0) + (v.y != 0);
#pragma unroll
        for (int o = 16; o; o >>= 1) c += __shfl_xor_sync(0xffffffffu, c, o);
        if ((tid & 31) == 0) atomicAdd(&s_len, c);
    }

    // ---- E packed in registers: pair x holds (E[2x], E[2x+1]) of my slice
    //      forward thread j: E[i] = exp(trans[i][j]) (column)
    //      backward thread i: E[i] = exp(trans[i][x]) (row) ----
    const float* tb = isF ? (trans + gc) : (trans + gc * TT);
    const int    ts = isF ? TT : 1;
    uint64_t E2[26];
#pragma unroll
    for (int x = 0; x < 26; x++) {
        int i0 = 2 * x, i1 = 2 * x + 1;
        float e0 = (gv && i0 < TT) ? ex2(tb[i0 * ts] * LOG2E) : 0.f;
        float e1 = (gv && i1 < TT) ? ex2(tb[i1 * ts] * LOG2E) : 0.f;
        PACK2(E2[x], e0, e1);
    }

    const float* fb = feats + (size_t)b * LL * TT;
    const float s0   = trans[STARTT * TT + 1];
    const float tref = trans[1 * TT + STOPT];
    const float C2f  = s0 * LOG2E;

    __syncthreads();
    const int len = s_len;
    const int nf  = (len - 1) >> 1;        // forward steps
    const int nb  = (len - 1) - nf;        // backward steps (>= nf)

    // ---- group inits (all 64 slots written; cols >= 50 exact zero) ----
    if (isF) {
        Ab[0][g] = gv ? ex2((fb[gc] + trans[STARTT * TT + gc] - s0) * LOG2E)
                      : 0.f;
    } else {
        float w = gv ? ex2((trans[gc * TT + STOPT] - tref) * LOG2E) : 0.f;
        float f = (nb > 0) ? ex2(fb[(len - 1) * TT + gc] * LOG2E) : 1.f;
        Bb[0][g] = gv ? w * f : 0.f;
    }
    int kacc = 0;

    // ---- distance-2 feats prefetch (clamped) ----
    int r1 = isF ? 1 : len - 2;
    int r2 = isF ? 2 : len - 3;
    r1 = min(max(r1, 0), len - 1);
    r2 = min(max(r2, 0), len - 1);
    float fc = fb[r1 * TT + gc];
    float fn = fb[r2 * TT + gc];

    float* Pc = isF ? Ab[0] : Bb[0];
    float* Pn = isF ? Ab[1] : Bb[1];
    barg(bid);

    // shared dot body: 26 FFMA2 + rotating accumulators + tree
#define CRF_DOT_BODY                                                        \
        unsigned sc_ = (unsigned)__cvta_generic_to_shared(Pc);              \
        uint64_t q0, q1;                                                    \
        uint64_t acc0, acc1, acc2, acc3, acc4, acc5, acc6, acc7;            \
        LDS_V2U64(q0, q1, sc_);                                             \
        uint64_t p0_ = q0, p1_ = q1;   /* kept for optional pivot */        \
        FMUL2(acc0, q0, E2[0]);                                             \
        FMUL2(acc1, q1, E2[1]);                                             \
        LDS_V2U64(q0, q1, sc_ + 16);                                        \
        FMUL2(acc2, q0, E2[2]);                                             \
        FMUL2(acc3, q1, E2[3]);                                             \
        LDS_V2U64(q0, q1, sc_ + 32);                                        \
        FMUL2(acc4, q0, E2[4]);                                             \
        FMUL2(acc5, q1, E2[5]);                                             \
        LDS_V2U64(q0, q1, sc_ + 48);                                        \
        FMUL2(acc6, q0, E2[6]);                                             \
        FMUL2(acc7, q1, E2[7]);                                             \
        _Pragma("unroll")                                                   \
        for (int q = 4; q < 13; q++) {                                      \
            LDS_V2U64(q0, q1, sc_ + q * 16);                                \
            FFMA2(acc0, q0, E2[2 * q], acc0);                               \
            FFMA2(acc1, q1, E2[2 * q + 1], acc1);                           \
            uint64_t t0 = acc0; acc0 = acc2; acc2 = acc4; acc4 = acc6;      \
            acc6 = t0;                                                      \
            uint64_t t1 = acc1; acc1 = acc3; acc3 = acc5; acc5 = acc7;      \
            acc7 = t1;                                                      \
        }                                                                   \
        FADD2(acc0, acc0, acc4);                                            \
        FADD2(acc1, acc1, acc5);                                            \
        FADD2(acc2, acc2, acc6);                                            \
        FADD2(acc3, acc3, acc7);                                            \
        FADD2(acc0, acc0, acc2);                                            \
        FADD2(acc1, acc1, acc3);                                            \
        FADD2(acc0, acc0, acc1);                                            \
        float lo_, hi_;                                                     \
        UNPACK2(lo_, hi_, acc0);

    // rescale step: pivot from P[1..3], exact pow2 bookkeeping
#define CRF_STEP_R(EFV)                                                     \
    {                                                                       \
        CRF_DOT_BODY                                                        \
        float pv0, pv1, pv2, pv3;                                           \
        UNPACK2(pv0, pv1, p0_);                                             \
        UNPACK2(pv2, pv3, p1_);                                             \
        float m_ = fmaxf(fmaxf(pv1, pv2), pv3);                             \
        int   k_ = (__float_as_int(m_) >> 23) - 127;                        \
        float sf = __int_as_float((127 - k_) << 23) * (EFV);                \
        Pn[g] = (lo_ + hi_) * sf;                                           \
        kacc += k_;                                                         \
        barg(bid);                                                          \
        float* _t = Pc; Pc = Pn; Pn = _t;                                   \
    }

    // plain step: no pivot, no scale bookkeeping
#define CRF_STEP_N(EFV)                                                     \
    {                                                                       \
        CRF_DOT_BODY                                                        \
        (void)p0_; (void)p1_;                                               \
        Pn[g] = (lo_ + hi_) * (EFV);                                        \
        barg(bid);                                                          \
        float* _t = Pc; Pc = Pn; Pn = _t;                                   \
    }

    if (isF) {
        int s = 1;
        for (; s + 1 <= nf; s += 2) {
            float ef0 = ex2(fc * LOG2E);
            fc = fn;
            int rn = min(s + 2, len - 1);
            fn = fb[rn * TT + gc];
            CRF_STEP_N(ef0);
            float ef1 = ex2(fc * LOG2E);
            fc = fn;
            rn = min(s + 3, len - 1);
            fn = fb[rn * TT + gc];
            CRF_STEP_R(ef1);
        }
        if (s <= nf) {
            float ef0 = ex2(fc * LOG2E);
            CRF_STEP_R(ef0);
        }
    } else {
        int s = 1;
        for (; s + 1 <= nb - 1; s += 2) {
            float ef0 = ex2(fc * LOG2E);
            fc = fn;
            int rn = max(len - 3 - s, 0);
            fn = fb[rn * TT + gc];
            CRF_STEP_N(ef0);
            float ef1 = ex2(fc * LOG2E);
            fc = fn;
            rn = max(len - 4 - s, 0);
            fn = fb[rn * TT + gc];
            CRF_STEP_R(ef1);
        }
        if (s <= nb - 1) {
            float ef0 = ex2(fc * LOG2E);
            CRF_STEP_R(ef0);
        }
        if (nb >= 1) {                  // final step: exclude ef_m
            CRF_STEP_R(1.0f);
        }
    }
#undef CRF_STEP_R
#undef CRF_STEP_N
#undef CRF_DOT_BODY

    // ---- combine at the midpoint: Z = sum_i alpha_m[i] * beta_m[i] ----
    if (tid == 0)  s_kf = kacc;
    if (tid == 64) s_kb = kacc;
    __syncthreads();
    float z = 0.f;
    if (isF && gv) z = Pc[g] * Bb[nb & 1][g];
    float sumv = blockSum(z, red);
    float fwd = (log2f(sumv) + C2f + (float)(s_kf + s_kb)) * LN2F + tref;

    // ---- gold score ----
    const int* tgb = tags + (size_t)b * LL;
    float gl = 0.f;
    for (int t = tid; t < len; t += NTH) {
        int tg = tgb[t];
        int pv = (t == 0) ? STARTT : tgb[t - 1];
        gl += fb[t * TT + tg] + trans[pv * TT + tg];
    }
    float gold = blockSum(gl, red);

    if (tid == 0) {
        gold += trans[tgb[len - 1] * TT + STOPT];
        g_partial[b] = fwd - gold;
    }

    // ---- fused finalize: last CTA sums all partials (fixed order) ----
    __threadfence();
    if (tid == 0) s_rank = atomicAdd(&g_done, 1u);
    __syncthreads();
    if (s_rank == gridDim.x - 1) {
        const int B = gridDim.x;
        if (tid < 32) {
            float acc = 0.f;
            for (int i = tid; i < B; i += 32) {
                float v;
                asm volatile("ld.global.cg.f32 %0, [%1];" : "=f"(v)
                             : "l"(&g_partial[i]));
                acc += v;
            }
#pragma unroll
            for (int o = 16; o; o >>= 1)
                acc += __shfl_xor_sync(0xffffffffu, acc, o);
            if (tid == 0) {
                *out = acc;
                g_done = 0;   // reset for next graph replay
            }
        }
    }
}

extern "C" void kernel_launch(void* const* d_in, const int* in_sizes, int n_in,
                              void* d_out, int out_size) {
    const float* feats = (const float*)d_in[0];
    const float* trans = (const float*)d_in[1];
    const int*   tags  = (const int*)d_in[2];
    const int*   mask  = (const int*)d_in[3];
    int B = in_sizes[0] / (LL * TT);

    crf_kernel<<<B, NTH>>>(feats, trans, tags, mask, (float*)d_out);
}

// round 16
// speedup vs baseline: 1.4525x; 1.1035x over previous
#include <cuda_runtime.h>
#include <cstdint>

// CRF loss via bidirectional scaled forward algorithm, f32x2-packed inner loop.
// One 128-thread CTA per batch row: warps 0-1 alpha forward (t=0..m), warps
// 2-3 beta backward (t=len-1..m); Z = sum_i alpha_m[i]*beta_m[i]. Each group
// has its own named barrier and tight loop. The 50-term dot product per
// thread runs as 26 fma.rn.f32x2 (packed fp32 pairs) on pairs loaded with
// ld.shared.v2.u64 against pre-packed E registers. Exact pow-2 rescaling per
// step from the exponent of max(P[1..3]). Prefetch indices unclamped in the
// hot loops (provably in-bounds: fwd s+2<=129<256; bwd len-3-s>=nf-1>=0).

constexpr int TT = 50;
constexpr int LL = 256;
constexpr int NTH = 128;
constexpr int STARTT = TT - 2;
constexpr int STOPT  = TT - 1;

#define LOG2E 1.4426950408889634f
#define LN2F  0.6931471805599453f

__device__ float    g_partial[1024];
__device__ unsigned g_done = 0;

__device__ __forceinline__ float ex2(float x) {
    float r;
    asm("ex2.approx.ftz.f32 %0, %1;" : "=f"(r) : "f"(x));
    return r;
}

__device__ __forceinline__ void barg(int id) {    // group barrier, 64 threads
    asm volatile("bar.sync %0, 64;" :: "r"(id));
}

#define PACK2(d, lo, hi) \
    asm("mov.b64 %0, {%1, %2};" : "=l"(d) : "f"(lo), "f"(hi))
#define UNPACK2(lo, hi, s) \
    asm("mov.b64 {%0, %1}, %2;" : "=f"(lo), "=f"(hi) : "l"(s))
#define FFMA2(d, a, b, c) \
    asm("fma.rn.f32x2 %0, %1, %2, %3;" : "=l"(d) : "l"(a), "l"(b), "l"(c))
#define FMUL2(d, a, b) \
    asm("mul.rn.f32x2 %0, %1, %2;" : "=l"(d) : "l"(a), "l"(b))
#define FADD2(d, a, b) \
    asm("add.rn.f32x2 %0, %1, %2;" : "=l"(d) : "l"(a), "l"(b))
#define LDS_V2U64(q0, q1, addr) \
    asm volatile("ld.shared.v2.u64 {%0, %1}, [%2];" \
                 : "=l"(q0), "=l"(q1) : "r"(addr))

__device__ __forceinline__ float blockSum(float v, volatile float* red) {
#pragma unroll
    for (int o = 16; o; o >>= 1) v += __shfl_xor_sync(0xffffffffu, v, o);
    if ((threadIdx.x & 31) == 0) red[threadIdx.x >> 5] = v;
    __syncthreads();
    v = (red[0] + red[1]) + (red[2] + red[3]);
    __syncthreads();
    return v;
}

__global__ void __launch_bounds__(NTH, 1)
crf_kernel(const float* __restrict__ feats, const float* __restrict__ trans,
           const int* __restrict__ tags, const int* __restrict__ mask,
           float* __restrict__ out) {
    __shared__ __align__(16) float Ab[2][64];   // alpha ping-pong
    __shared__ __align__(16) float Bb[2][64];   // beta  ping-pong
    __shared__ float red[4];
    __shared__ int s_len, s_kf, s_kb;
    __shared__ unsigned s_rank;

    const int b    = blockIdx.x;
    const int tid  = threadIdx.x;
    const bool isF = (tid < 64);       // forward group = warps 0-1
    const int g    = tid & 63;         // state index within group
    const bool gv  = (g < TT);
    const int gc   = gv ? g : (TT - 1);
    const int bid  = isF ? 1 : 2;

    if (tid == 0) s_len = 0;
    __syncthreads();

    // ---- sequence length (mask is a 0/1 prefix) ----
    {
        const int2* m2 = (const int2*)(mask + (size_t)b * LL);
        int2 v = m2[tid];
        int c = (v.x != 0) + (v.y != 0);
#pragma unroll
        for (int o = 16; o; o >>= 1) c += __shfl_xor_sync(0xffffffffu, c, o);
        if ((tid & 31) == 0) atomicAdd(&s_len, c);
    }

    // ---- E packed in registers: pair x holds (E[2x], E[2x+1]) of my slice
    //      forward thread j: E[i] = exp(trans[i][j]) (column)
    //      backward thread i: E[i] = exp(trans[i][x]) (row) ----
    const float* tb = isF ? (trans + gc) : (trans + gc * TT);
    const int    ts = isF ? TT : 1;
    uint64_t E2[26];
#pragma unroll
    for (int x = 0; x < 26; x++) {
        int i0 = 2 * x, i1 = 2 * x + 1;
        float e0 = (gv && i0 < TT) ? ex2(tb[i0 * ts] * LOG2E) : 0.f;
        float e1 = (gv && i1 < TT) ? ex2(tb[i1 * ts] * LOG2E) : 0.f;
        PACK2(E2[x], e0, e1);
    }

    const float* fb = feats + (size_t)b * LL * TT;
    const float s0   = trans[STARTT * TT + 1];
    const float tref = trans[1 * TT + STOPT];
    const float C2f  = s0 * LOG2E;

    __syncthreads();
    const int len = s_len;
    const int nf  = (len - 1) >> 1;        // forward steps
    const int nb  = (len - 1) - nf;        // backward steps (>= nf)

    // ---- group inits (all 64 slots written; cols >= 50 exact zero) ----
    if (isF) {
        Ab[0][g] = gv ? ex2((fb[gc] + trans[STARTT * TT + gc] - s0) * LOG2E)
                      : 0.f;
    } else {
        float w = gv ? ex2((trans[gc * TT + STOPT] - tref) * LOG2E) : 0.f;
        float f = (nb > 0) ? ex2(fb[(len - 1) * TT + gc] * LOG2E) : 1.f;
        Bb[0][g] = gv ? w * f : 0.f;
    }
    int kacc = 0;

    // ---- distance-2 feats prefetch (clamped once at init only) ----
    int r1 = isF ? 1 : len - 2;
    int r2 = isF ? 2 : len - 3;
    r1 = min(max(r1, 0), len - 1);
    r2 = min(max(r2, 0), len - 1);
    float fc = fb[r1 * TT + gc];
    float fn = fb[r2 * TT + gc];

    float* Pc = isF ? Ab[0] : Bb[0];
    float* Pn = isF ? Ab[1] : Bb[1];
    barg(bid);

    // one step: packed 52-term dot (26 FFMA2) + exact pow2 rescale + store
#define CRF_STEP(EFV)                                                       \
    {                                                                       \
        unsigned sc_ = (unsigned)__cvta_generic_to_shared(Pc);              \
        uint64_t q0, q1;                                                    \
        uint64_t acc0, acc1, acc2, acc3, acc4, acc5, acc6, acc7;            \
        LDS_V2U64(q0, q1, sc_);                                             \
        /* pivot from pair q1 = (P[2],P[3]) and q0.hi = P[1] */             \
        float pv0, pv1, pv2, pv3;                                           \
        UNPACK2(pv0, pv1, q0);                                              \
        UNPACK2(pv2, pv3, q1);                                              \
        float m_ = fmaxf(fmaxf(pv1, pv2), pv3);                             \
        int   k_ = (__float_as_int(m_) >> 23) - 127;                        \
        float sf = __int_as_float((127 - k_) << 23) * (EFV);                \
        FMUL2(acc0, q0, E2[0]);                                             \
        FMUL2(acc1, q1, E2[1]);                                             \
        LDS_V2U64(q0, q1, sc_ + 16);                                        \
        FMUL2(acc2, q0, E2[2]);                                             \
        FMUL2(acc3, q1, E2[3]);                                             \
        LDS_V2U64(q0, q1, sc_ + 32);                                        \
        FMUL2(acc4, q0, E2[4]);                                             \
        FMUL2(acc5, q1, E2[5]);                                             \
        LDS_V2U64(q0, q1, sc_ + 48);                                        \
        FMUL2(acc6, q0, E2[6]);                                             \
        FMUL2(acc7, q1, E2[7]);                                             \
        _Pragma("unroll")                                                   \
        for (int q = 4; q < 13; q++) {                                      \
            LDS_V2U64(q0, q1, sc_ + q * 16);                                \
            FFMA2(acc0, q0, E2[2 * q], acc0);                               \
            FFMA2(acc1, q1, E2[2 * q + 1], acc1);                           \
            uint64_t t0 = acc0; acc0 = acc2; acc2 = acc4; acc4 = acc6;      \
            acc6 = t0;                                                      \
            uint64_t t1 = acc1; acc1 = acc3; acc3 = acc5; acc5 = acc7;      \
            acc7 = t1;                                                      \
        }                                                                   \
        FADD2(acc0, acc0, acc4);                                            \
        FADD2(acc1, acc1, acc5);                                            \
        FADD2(acc2, acc2, acc6);                                            \
        FADD2(acc3, acc3, acc7);                                            \
        FADD2(acc0, acc0, acc2);                                            \
        FADD2(acc1, acc1, acc3);                                            \
        FADD2(acc0, acc0, acc1);                                            \
        float lo_, hi_;                                                     \
        UNPACK2(lo_, hi_, acc0);                                            \
        Pn[g] = (lo_ + hi_) * sf;                                           \
        kacc += k_;                                                         \
        barg(bid);                                                          \
        float* _t = Pc; Pc = Pn; Pn = _t;                                   \
    }

    if (isF) {
        for (int s = 1; s <= nf; ++s) {
            float efv = ex2(fc * LOG2E);
            fc = fn;
            fn = fb[(s + 2) * TT + gc];       // s+2 <= 129 < LL: in-bounds
            CRF_STEP(efv);
        }
    } else {
        for (int s = 1; s < nb; ++s) {
            float efv = ex2(fc * LOG2E);
            fc = fn;
            fn = fb[(len - 3 - s) * TT + gc]; // >= nf-1 >= 0 when loop runs
            CRF_STEP(efv);
        }
        if (nb >= 1) {                  // final step: exclude ef_m
            CRF_STEP(1.0f);
        }
    }
#undef CRF_STEP

    // ---- combine at the midpoint: Z = sum_i alpha_m[i] * beta_m[i] ----
    if (tid == 0)  s_kf = kacc;
    if (tid == 64) s_kb = kacc;
    __syncthreads();
    float z = 0.f;
    if (isF && gv) z = Pc[g] * Bb[nb & 1][g];
    float sumv = blockSum(z, red);
    float fwd = (log2f(sumv) + C2f + (float)(s_kf + s_kb)) * LN2F + tref;

    // ---- gold score ----
    const int* tgb = tags + (size_t)b * LL;
    float gl = 0.f;
    for (int t = tid; t < len; t += NTH) {
        int tg = tgb[t];
        int pv = (t == 0) ? STARTT : tgb[t - 1];
        gl += fb[t * TT + tg] + trans[pv * TT + tg];
    }
    float gold = blockSum(gl, red);

    if (tid == 0) {
        gold += trans[tgb[len - 1] * TT + STOPT];
        g_partial[b] = fwd - gold;
    }

    // ---- fused finalize: last CTA sums all partials (fixed order) ----
    __threadfence();
    if (tid == 0) s_rank = atomicAdd(&g_done, 1u);
    __syncthreads();
    if (s_rank == gridDim.x - 1) {
        const int B = gridDim.x;
        if (tid < 32) {
            float acc = 0.f;
            for (int i = tid; i < B; i += 32) {
                float v;
                asm volatile("ld.global.cg.f32 %0, [%1];" : "=f"(v)
                             : "l"(&g_partial[i]));
                acc += v;
            }
#pragma unroll
            for (int o = 16; o; o >>= 1)
                acc += __shfl_xor_sync(0xffffffffu, acc, o);
            if (tid == 0) {
                *out = acc;
                g_done = 0;   // reset for next graph replay
            }
        }
    }
}

extern "C" void kernel_launch(void* const* d_in, const int* in_sizes, int n_in,
                              void* d_out, int out_size) {
    const float* feats = (const float*)d_in[0];
    const float* trans = (const float*)d_in[1];
    const int*   tags  = (const int*)d_in[2];
    const int*   mask  = (const int*)d_in[3];
    int B = in_sizes[0] / (LL * TT);

    crf_kernel<<<B, NTH>>>(feats, trans, tags, mask, (float*)d_out);
}